// round 10
// baseline (speedup 1.0000x reference)
#include <cuda_runtime.h>
#include <cuda_bf16.h>
#include <cuda_fp16.h>
#include <math.h>

// Problem dims
#define B_    64
#define HDIM  1024
#define SLEN  256
#define GDIM  4096      // 4*H
#define EDIM  512
#define IN0   1536

#define STGB  16384     // one k32 stage buffer: 16KB
#define NBUF  4         // ring depth

// ---------------- device scratch (no allocs allowed) ----------------
__device__ float g_xw[67108864];        // [S][B][4H] (268MB): xw + pre0 folded in
__device__ float g_pre0[B_ * GDIM];     // static-part gate precompute (incl. biases l0)
__device__ float g_bias1[GDIM];         // b_ih1 + b_hh1
__device__ uint4 g_wph[1572864];        // fp16 packed weights: [mat(3)][n32(128)][k16(64)][half(2)][lane(32)] (24MB)
__device__ uint4 g_h0p[16384];          // fp16 packed h0 ping-pong: [slot(2)][wm(2)][k16(64)][mt(2)][lane(32)]
__device__ uint4 g_h1p[16384];          // fp16 packed h1 ping-pong
__device__ float g_c0[B_ * HDIM];
__device__ float g_c1[B_ * HDIM];

// grid barrier state
__device__ volatile unsigned g_bar_cnt;
__device__ volatile unsigned g_bar_gen;

// ---------------- helpers ----------------
__device__ __forceinline__ unsigned f2tf(float x) {
    unsigned u;
    asm("cvt.rna.tf32.f32 %0, %1;" : "=r"(u) : "f"(x));
    return u;
}

__device__ __forceinline__ unsigned pkh(float a, float b) {
    __half2 h = __halves2half2(__float2half_rn(a), __float2half_rn(b));
    return *(unsigned*)&h;
}

__device__ __forceinline__ void mma8(float d[4], const unsigned a[4], const unsigned b[2]) {
    asm volatile(
        "mma.sync.aligned.m16n8k8.row.col.f32.tf32.tf32.f32 "
        "{%0,%1,%2,%3}, {%4,%5,%6,%7}, {%8,%9}, {%0,%1,%2,%3};\n"
        : "+f"(d[0]), "+f"(d[1]), "+f"(d[2]), "+f"(d[3])
        : "r"(a[0]), "r"(a[1]), "r"(a[2]), "r"(a[3]), "r"(b[0]), "r"(b[1]));
}

__device__ __forceinline__ void mma16(float d[4], const unsigned a[4], const unsigned b[2]) {
    asm volatile(
        "mma.sync.aligned.m16n8k16.row.col.f32.f16.f16.f32 "
        "{%0,%1,%2,%3}, {%4,%5,%6,%7}, {%8,%9}, {%0,%1,%2,%3};\n"
        : "+f"(d[0]), "+f"(d[1]), "+f"(d[2]), "+f"(d[3])
        : "r"(a[0]), "r"(a[1]), "r"(a[2]), "r"(a[3]), "r"(b[0]), "r"(b[1]));
}

__device__ __forceinline__ float sigm(float x) { return 1.0f / (1.0f + __expf(-x)); }

__device__ __forceinline__ unsigned smem_u32(const void* p) {
    unsigned a;
    asm("{ .reg .u64 t; cvta.to.shared.u64 t, %1; cvt.u32.u64 %0, t; }" : "=r"(a) : "l"(p));
    return a;
}

// mbarrier primitives
__device__ __forceinline__ void mb_init(unsigned addr, unsigned cnt) {
    asm volatile("mbarrier.init.shared::cta.b64 [%0], %1;" :: "r"(addr), "r"(cnt) : "memory");
}
__device__ __forceinline__ void mb_arrive(unsigned addr) {
    asm volatile("mbarrier.arrive.shared::cta.b64 _, [%0];" :: "r"(addr) : "memory");
}
__device__ __forceinline__ void mb_expect_tx(unsigned addr, unsigned bytes) {
    asm volatile("mbarrier.arrive.expect_tx.shared::cta.b64 _, [%0], %1;"
                 :: "r"(addr), "r"(bytes) : "memory");
}
__device__ __forceinline__ void mb_wait(unsigned addr, unsigned parity) {
    asm volatile(
        "{\n\t.reg .pred P;\n"
        "W%=:\n\t"
        "mbarrier.try_wait.parity.shared::cta.b64 P, [%0], %1, 0x989680;\n\t"
        "@P bra D%=;\n\t"
        "bra W%=;\n"
        "D%=:\n\t}"
        :: "r"(addr), "r"(parity) : "memory");
}
__device__ __forceinline__ void bulk1k(unsigned dst, const uint4* src, unsigned mbar) {
    asm volatile(
        "cp.async.bulk.shared::cta.global.mbarrier::complete_tx::bytes [%0], [%1], 1024, [%2];"
        :: "r"(dst), "l"(src), "r"(mbar) : "memory");
}

// packed-h half index within one slot (65536 halves per slot)
__device__ __forceinline__ int hp_idx(int b, int hh) {
    int wm = b >> 5;
    int mt = (b >> 4) & 1;
    int r8 = (b >> 3) & 1;
    int lane = ((b & 7) << 2) | ((hh >> 1) & 3);
    int k16 = hh >> 4;
    int reg = (((hh >> 3) & 1) << 1) | r8;
    return ((((wm << 6) | k16) * 2 + mt) * 32 + lane) * 8 + reg * 2 + (hh & 1);
}

// ---------------- init: encoder state -> packed h buffers + c ----------------
__global__ void init_pack_kernel(const float* __restrict__ eh, const float* __restrict__ ec) {
    int i = blockIdx.x * blockDim.x + threadIdx.x;
    if (i < B_ * HDIM) {
        int b = i >> 10, hh = i & 1023;
        ((__half*)g_h0p)[65536 + hp_idx(b, hh)] = __float2half_rn(eh[i]);
        ((__half*)g_h1p)[65536 + hp_idx(b, hh)] = __float2half_rn(eh[B_ * HDIM + i]);
        g_c0[i] = ec[i];
        g_c1[i] = ec[B_ * HDIM + i];
    }
}

// ---------------- bias1 fold ----------------
__global__ void bias1_kernel(const float* __restrict__ b_ih1, const float* __restrict__ b_hh1) {
    int i = blockIdx.x * blockDim.x + threadIdx.x;
    if (i < GDIM) g_bias1[i] = b_ih1[i] + b_hh1[i];
}

// ---------------- fp16 weight pre-pack into mma fragment order ----------------
// hot-loop index: mat*524288 + n32*4096 + k16*64 + half*32 + lane
__global__ void pack_w_kernel(const float* __restrict__ W0, const float* __restrict__ W1,
                              const float* __restrict__ W2) {
    int g = blockIdx.x * 256 + threadIdx.x;   // 1,572,864 total
    int lane = g & 31;
    int hf   = (g >> 5) & 1;
    int k16  = (g >> 6) & 63;
    int n32  = (g >> 12) & 127;
    int mat  = g >> 19;
    const float* W = (mat == 0) ? W0 : ((mat == 1) ? W1 : W2);
    int bxm = n32 >> 1, wn = n32 & 1;
    int n0 = wn * 32 + hf * 16 + (lane >> 2);
    int n1 = n0 + 8;
    // quadrant-gathered column map: j = (n>>4)*1024 + bxm*16 + (n&15)
    int j0 = ((n0 >> 4) << 10) + (bxm << 4) + (n0 & 15);
    int j1 = ((n1 >> 4) << 10) + (bxm << 4) + (n1 & 15);
    int k0 = k16 * 16 + 2 * (lane & 3);
    const float* r0 = W + (size_t)j0 * HDIM + k0;
    const float* r1 = W + (size_t)j1 * HDIM + k0;
    uint4 v;
    v.x = pkh(r0[0], r0[1]);  v.y = pkh(r0[8], r0[9]);
    v.z = pkh(r1[0], r1[1]);  v.w = pkh(r1[8], r1[9]);
    g_wph[g] = v;
}

// ---------------- pre0: biases + static part of layer-0 gates ----------------
__global__ void __launch_bounds__(256) pre0_kernel(
    const float* __restrict__ enc_outs, const int* __restrict__ langs,
    const float* __restrict__ embed, const float* __restrict__ W_ih0,
    const float* __restrict__ b_ih0, const float* __restrict__ b_hh0)
{
    __shared__ float red[256];
    const int j = blockIdx.x;
    const int t = threadIdx.x;
    const int b = t >> 2, kq = t & 3;
    const float* Wrow = W_ih0 + (size_t)j * IN0 + 512;
    const int lang = langs[b];
    const int k0 = kq * 256;
    float acc = 0.0f;
    if (kq < 2) {
        const float* src = enc_outs + (b * 128 + 127) * 512 + k0;
        #pragma unroll 8
        for (int kk = 0; kk < 256; kk++) acc += src[kk] * Wrow[k0 + kk];
    } else {
        const float* src = embed + (size_t)lang * EDIM + (k0 - 512);
        #pragma unroll 8
        for (int kk = 0; kk < 256; kk++) acc += src[kk] * Wrow[k0 + kk];
    }
    red[t] = acc;
    __syncthreads();
    if (kq == 0) {
        float s = red[t] + red[t + 1] + red[t + 2] + red[t + 3];
        g_pre0[b * GDIM + j] = s + b_ih0[j] + b_hh0[j];
    }
}

// ---------------- xw: big precompute GEMM (+ pre0 folded at store) ----------------
__global__ void __launch_bounds__(256) xw_kernel(
    const int* __restrict__ prev, const float* __restrict__ embed,
    const float* __restrict__ W_ih0)
{
    __shared__ unsigned As[128][36];
    __shared__ unsigned Bs[64][36];
    __shared__ int toks[128];
    const int tid = threadIdx.x, lane = tid & 31, warp = tid >> 5;
    const int wm = warp >> 1, wn = warp & 1;
    const int bx = blockIdx.x;
    const int by = blockIdx.y;

    if (tid < 128) {
        int r = by * 128 + tid;
        toks[tid] = prev[(r & 63) * SLEN + (r >> 6)];
    }
    __syncthreads();

    float acc[2][4][4];
    #pragma unroll
    for (int i = 0; i < 2; i++)
        #pragma unroll
        for (int jj = 0; jj < 4; jj++)
            #pragma unroll
            for (int k = 0; k < 4; k++) acc[i][jj][k] = 0.0f;

    for (int k0 = 0; k0 < EDIM; k0 += 32) {
        #pragma unroll
        for (int r = 0; r < 4; r++) {
            int idx = tid + r * 256;
            int row = idx >> 3, c4 = idx & 7;
            float4 v = *(const float4*)(embed + (size_t)toks[row] * EDIM + k0 + c4 * 4);
            As[row][c4 * 4 + 0] = f2tf(v.x); As[row][c4 * 4 + 1] = f2tf(v.y);
            As[row][c4 * 4 + 2] = f2tf(v.z); As[row][c4 * 4 + 3] = f2tf(v.w);
        }
        #pragma unroll
        for (int r = 0; r < 2; r++) {
            int idx = tid + r * 256;
            int n = idx >> 3, c4 = idx & 7;
            int j = bx * 64 + n;
            float4 v = *(const float4*)(W_ih0 + (size_t)j * IN0 + k0 + c4 * 4);
            Bs[n][c4 * 4 + 0] = f2tf(v.x); Bs[n][c4 * 4 + 1] = f2tf(v.y);
            Bs[n][c4 * 4 + 2] = f2tf(v.z); Bs[n][c4 * 4 + 3] = f2tf(v.w);
        }
        __syncthreads();
        #pragma unroll
        for (int kc = 0; kc < 4; kc++) {
            const int kb = kc * 8 + (lane & 3);
            unsigned a[2][4], b[4][2];
            #pragma unroll
            for (int mt = 0; mt < 2; mt++) {
                int r0 = wm * 32 + mt * 16 + (lane >> 2);
                a[mt][0] = As[r0][kb];     a[mt][1] = As[r0 + 8][kb];
                a[mt][2] = As[r0][kb + 4]; a[mt][3] = As[r0 + 8][kb + 4];
            }
            #pragma unroll
            for (int nt = 0; nt < 4; nt++) {
                int n0 = wn * 32 + nt * 8 + (lane >> 2);
                b[nt][0] = Bs[n0][kb]; b[nt][1] = Bs[n0][kb + 4];
            }
            #pragma unroll
            for (int mt = 0; mt < 2; mt++)
                #pragma unroll
                for (int nt = 0; nt < 4; nt++)
                    mma8(acc[mt][nt], a[mt], b[nt]);
        }
        __syncthreads();
    }
    #pragma unroll
    for (int mt = 0; mt < 2; mt++)
        #pragma unroll
        for (int nt = 0; nt < 4; nt++) {
            int row = wm * 32 + mt * 16 + (lane >> 2);
            int col = bx * 64 + wn * 32 + nt * 8 + 2 * (lane & 3);
            int rg0 = by * 128 + row;
            int rg1 = rg0 + 8;
            size_t base0 = (size_t)rg0 * GDIM + col;
            size_t base1 = (size_t)rg1 * GDIM + col;
            const float* p0 = g_pre0 + (rg0 & 63) * GDIM + col;
            const float* p1 = g_pre0 + (rg1 & 63) * GDIM + col;
            *(float2*)(g_xw + base0) = make_float2(acc[mt][nt][0] + p0[0], acc[mt][nt][1] + p0[1]);
            *(float2*)(g_xw + base1) = make_float2(acc[mt][nt][2] + p1[0], acc[mt][nt][3] + p1[1]);
        }
}

// ---------------- grid-wide barrier (all 128 CTAs co-resident) ----------------
__device__ __forceinline__ void grid_sync() {
    __syncthreads();
    if (threadIdx.x == 0) {
        unsigned gen = g_bar_gen;
        __threadfence();
        if (atomicAdd((unsigned*)&g_bar_cnt, 1u) == 127u) {
            g_bar_cnt = 0;
            __threadfence();
            g_bar_gen = gen + 1;
        } else {
            while (g_bar_gen == gen) { __nanosleep(16); }
        }
        __threadfence();
    }
    __syncthreads();
}

// ---------------- persistent LSTM kernel ----------------
// CTAs 0..63: layer0 step t=i.  CTAs 64..127: layer1 step t=i-1.  One grid barrier/iter.
// 8 warps: wn = w&1, wm = (w>>1)&1, wk = w>>2 (split-K half / matrix select).
// Producer: thread 0 issues TMA bulk copies into a 4-deep mbarrier ring of k32 stages.
// Stage (16KB, uint4 idx): j(2)*512 + { A: wk*128+wm*64+mt*32+lane ; W: 256 + wk*128+wn*64+half*32+lane }
__global__ void __launch_bounds__(256, 1) persist_kernel(float* __restrict__ out) {
    extern __shared__ uint4 dynsmem[];
    uint4* stg = dynsmem;                            // 4 * 1024 uint4 = 64KB
    float* gsr = (float*)(dynsmem + NBUF * 1024);    // 64*68 floats = 17408B
    unsigned smem0 = smem_u32(dynsmem);
    const unsigned mb_off = smem0 + NBUF * STGB + 17408;   // barriers after gsr
    // full[i] at mb_off + i*8, empty[i] at mb_off + 32 + i*8

    const int tid = threadIdx.x, lane = tid & 31, warp = tid >> 5;
    const int wn = warp & 1, wm = (warp >> 1) & 1, wk = warp >> 2;
    const int bx = blockIdx.x;
    const bool isl0 = bx < 64;
    const int cx = isl0 ? bx : bx - 64;
    const int NS = isl0 ? 16 : 32;   // k32 stages per iter

    if (tid == 0) {
        #pragma unroll
        for (int i = 0; i < NBUF; i++) {
            mb_init(mb_off + i * 8, 1);            // full: 1 expect_tx arrive
            mb_init(mb_off + 32 + i * 8, 256);     // empty: all threads arrive
        }
    }
    __syncthreads();

    unsigned prod_cnt = 0, cons_cnt = 0;

    for (int i = 0; i <= 256; i++) {
        const int pa = (i + 1) & 1;
        const int pb = i & 1;
        const bool active = isl0 ? (i < 256) : (i >= 1);
        if (active) {
            const int t = isl0 ? i : i - 1;

            float acc[2][4][4];
            #pragma unroll
            for (int a = 0; a < 2; a++)
                #pragma unroll
                for (int b = 0; b < 4; b++)
                    #pragma unroll
                    for (int c = 0; c < 4; c++) acc[a][b][c] = 0.0f;

            // -------- producer lambda (thread 0 only) --------
            auto issue = [&](int r) {
                int b2 = prod_cnt & (NBUF - 1);
                unsigned u = prod_cnt >> 2;
                if (u >= 1) mb_wait(mb_off + 32 + b2 * 8, (u - 1) & 1);
                unsigned fullb = mb_off + b2 * 8;
                mb_expect_tx(fullb, STGB);
                unsigned dst0 = smem0 + b2 * STGB;
                #pragma unroll
                for (int j = 0; j < 2; j++) {
                    #pragma unroll
                    for (int w = 0; w < 2; w++) {
                        int k16 = isl0 ? (w * 32 + 2 * r + j) : (2 * r + j);
                        #pragma unroll
                        for (int q = 0; q < 2; q++) {
                            const uint4* asrc;
                            if (isl0) asrc = g_h0p + pa * 8192 + q * 4096 + k16 * 64;
                            else      asrc = (w ? g_h1p + pb * 8192 : g_h0p + pa * 8192)
                                             + q * 4096 + k16 * 64;
                            bulk1k(dst0 + (unsigned)(j * 512 + w * 128 + q * 64) * 16, asrc, fullb);
                            int mat = isl0 ? 0 : 1 + w;
                            const uint4* wsrc = g_wph + (size_t)mat * 524288
                                                + (cx * 2 + q) * 4096 + k16 * 64;
                            bulk1k(dst0 + (unsigned)(j * 512 + 256 + w * 128 + q * 64) * 16, wsrc, fullb);
                        }
                    }
                }
                prod_cnt++;
            };

            if (tid == 0) {
                issue(0); issue(1); issue(2);
            }

            for (int c = 0; c < NS; c++) {
                int b2 = cons_cnt & (NBUF - 1);
                mb_wait(mb_off + b2 * 8, (cons_cnt >> 2) & 1);
                if (tid == 0 && c + 3 < NS) issue(c + 3);
                const uint4* sb = stg + b2 * 1024;
                #pragma unroll
                for (int j = 0; j < 2; j++) {
                    const uint4* Ac = sb + j * 512 + wk * 128 + wm * 64;
                    const uint4* Wc = sb + j * 512 + 256 + wk * 128 + wn * 64;
                    uint4 a0 = Ac[lane], a1 = Ac[32 + lane];
                    uint4 w0 = Wc[lane], w1 = Wc[32 + lane];
                    unsigned A0[4] = {a0.x, a0.y, a0.z, a0.w};
                    unsigned A1[4] = {a1.x, a1.y, a1.z, a1.w};
                    unsigned B0[2] = {w0.x, w0.y}, B1[2] = {w0.z, w0.w};
                    unsigned B2[2] = {w1.x, w1.y}, B3[2] = {w1.z, w1.w};
                    mma16(acc[0][0], A0, B0); mma16(acc[0][1], A0, B1);
                    mma16(acc[0][2], A0, B2); mma16(acc[0][3], A0, B3);
                    mma16(acc[1][0], A1, B0); mma16(acc[1][1], A1, B1);
                    mma16(acc[1][2], A1, B2); mma16(acc[1][3], A1, B3);
                }
                mb_arrive(mb_off + 32 + b2 * 8);
                cons_cnt++;
            }
            __syncthreads();

            // split-K reduce via smem: wk=1 stores, wk=0 adds
            if (wk == 1) {
                #pragma unroll
                for (int mt = 0; mt < 2; mt++)
                    #pragma unroll
                    for (int nt = 0; nt < 4; nt++) {
                        int row = wm * 32 + mt * 16 + (lane >> 2);
                        int col = wn * 32 + nt * 8 + 2 * (lane & 3);
                        gsr[row * 68 + col]           = acc[mt][nt][0];
                        gsr[row * 68 + col + 1]       = acc[mt][nt][1];
                        gsr[(row + 8) * 68 + col]     = acc[mt][nt][2];
                        gsr[(row + 8) * 68 + col + 1] = acc[mt][nt][3];
                    }
            }
            __syncthreads();
            if (wk == 0) {
                #pragma unroll
                for (int mt = 0; mt < 2; mt++)
                    #pragma unroll
                    for (int nt = 0; nt < 4; nt++) {
                        int row = wm * 32 + mt * 16 + (lane >> 2);
                        int col = wn * 32 + nt * 8 + 2 * (lane & 3);
                        gsr[row * 68 + col]           += acc[mt][nt][0];
                        gsr[row * 68 + col + 1]       += acc[mt][nt][1];
                        gsr[(row + 8) * 68 + col]     += acc[mt][nt][2];
                        gsr[(row + 8) * 68 + col + 1] += acc[mt][nt][3];
                    }
            }
            __syncthreads();

            __half* hp_out = isl0 ? ((__half*)g_h0p + pb * 65536)
                                  : ((__half*)g_h1p + pa * 65536);
            const float* xw_t = g_xw + (size_t)t * (B_ * GDIM);
            float* cc = isl0 ? g_c0 : g_c1;

            #pragma unroll
            for (int ee = 0; ee < 4; ee++) {
                int e = tid + ee * 256;
                int b = e >> 4, u = e & 15;
                int hh = (cx << 4) + u;
                float g0, g1, g2, g3;
                if (isl0) {
                    g0 = gsr[b * 68 + u]      + xw_t[b * GDIM + hh];
                    g1 = gsr[b * 68 + 16 + u] + xw_t[b * GDIM + 1024 + hh];
                    g2 = gsr[b * 68 + 32 + u] + xw_t[b * GDIM + 2048 + hh];
                    g3 = gsr[b * 68 + 48 + u] + xw_t[b * GDIM + 3072 + hh];
                } else {
                    g0 = gsr[b * 68 + u]      + g_bias1[hh];
                    g1 = gsr[b * 68 + 16 + u] + g_bias1[1024 + hh];
                    g2 = gsr[b * 68 + 32 + u] + g_bias1[2048 + hh];
                    g3 = gsr[b * 68 + 48 + u] + g_bias1[3072 + hh];
                }
                float ci = cc[b * HDIM + hh];
                float cn = sigm(g1) * ci + sigm(g0) * tanhf(g2);
                cc[b * HDIM + hh] = cn;
                float hn = sigm(g3) * tanhf(cn);
                hp_out[hp_idx(b, hh)] = __float2half_rn(hn);
                if (!isl0) out[(size_t)t * (B_ * HDIM) + b * HDIM + hh] = hn;
            }
        }
        grid_sync();
    }
}

// ---------------- launch ----------------
extern "C" void kernel_launch(void* const* d_in, const int* in_sizes, int n_in,
                              void* d_out, int out_size) {
    const int*   prev   = (const int*)d_in[0];
    const int*   langs  = (const int*)d_in[1];
    const float* enc_o  = (const float*)d_in[2];
    const float* enc_h  = (const float*)d_in[3];
    const float* enc_c  = (const float*)d_in[4];
    const float* embed  = (const float*)d_in[5];
    const float* W_ih0  = (const float*)d_in[6];
    const float* W_hh0  = (const float*)d_in[7];
    const float* b_ih0  = (const float*)d_in[8];
    const float* b_hh0  = (const float*)d_in[9];
    const float* W_ih1  = (const float*)d_in[10];
    const float* W_hh1  = (const float*)d_in[11];
    const float* b_ih1  = (const float*)d_in[12];
    const float* b_hh1  = (const float*)d_in[13];
    float* out = (float*)d_out;

    const int smem_bytes = NBUF * STGB + 17408 + 64;   // 64KB stages + gsr + mbarriers
    static int attr_done = 0;
    if (!attr_done) {
        cudaFuncSetAttribute(persist_kernel, cudaFuncAttributeMaxDynamicSharedMemorySize,
                             smem_bytes);
        attr_done = 1;
    }

    init_pack_kernel<<<256, 256>>>(enc_h, enc_c);
    bias1_kernel<<<16, 256>>>(b_ih1, b_hh1);
    pack_w_kernel<<<6144, 256>>>(W_hh0, W_ih1, W_hh1);
    pre0_kernel<<<GDIM, 256>>>(enc_o, langs, embed, W_ih0, b_ih0, b_hh0);
    xw_kernel<<<dim3(GDIM / 64, (SLEN * B_) / 128), 256>>>(prev, embed, W_ih0);

    persist_kernel<<<128, 256, smem_bytes>>>(out);
}

// round 11
// speedup vs baseline: 1.7242x; 1.7242x over previous
#include <cuda_runtime.h>
#include <cuda_bf16.h>
#include <cuda_fp16.h>
#include <math.h>

// Problem dims
#define B_    1024
#undef B_
#define B_    64
#define HDIM  1024
#define SLEN  256
#define GDIM  4096      // 4*H
#define EDIM  512
#define IN0   1536

#define DEPTH 8         // cp.async ring buffers (k16 granularity, 8KB each)

// ---------------- device scratch (no allocs allowed) ----------------
__device__ float g_xw[67108864];        // [S][B][4H] (268MB): xw + pre0 folded in
__device__ float g_pre0[B_ * GDIM];     // static-part gate precompute (incl. biases l0)
__device__ float g_bias1[GDIM];         // b_ih1 + b_hh1
__device__ uint4 g_wph[1572864];        // fp16 packed weights: [mat(3)][n32(128)][k16(64)][half(2)][lane(32)] (24MB)
__device__ uint4 g_h0p[16384];          // fp16 packed h0 ping-pong: [slot(2)][wm(2)][k16(64)][mt(2)][lane(32)]
__device__ uint4 g_h1p[16384];          // fp16 packed h1 ping-pong
__device__ float g_c0[B_ * HDIM];
__device__ float g_c1[B_ * HDIM];

// grid barrier state
__device__ volatile unsigned g_bar_cnt;
__device__ volatile unsigned g_bar_gen;

// ---------------- helpers ----------------
__device__ __forceinline__ unsigned pkh(float a, float b) {
    __half2 h = __halves2half2(__float2half_rn(a), __float2half_rn(b));
    return *(unsigned*)&h;
}

// fp16 m16n8k16, f32 accumulate
__device__ __forceinline__ void mma16(float d[4], const unsigned a[4], const unsigned b[2]) {
    asm volatile(
        "mma.sync.aligned.m16n8k16.row.col.f32.f16.f16.f32 "
        "{%0,%1,%2,%3}, {%4,%5,%6,%7}, {%8,%9}, {%0,%1,%2,%3};\n"
        : "+f"(d[0]), "+f"(d[1]), "+f"(d[2]), "+f"(d[3])
        : "r"(a[0]), "r"(a[1]), "r"(a[2]), "r"(a[3]), "r"(b[0]), "r"(b[1]));
}

__device__ __forceinline__ float sigm(float x) { return 1.0f / (1.0f + __expf(-x)); }

// packed-h half index within one slot (65536 halves per slot)
// uint4 layout: [wm(2)][k16(64)][mt(2)][lane(32)], uint4 = {a0,a1,a2,a3} f16x2 regs
__device__ __forceinline__ int hp_idx(int b, int hh) {
    int wm = b >> 5;
    int mt = (b >> 4) & 1;
    int r8 = (b >> 3) & 1;
    int lane = ((b & 7) << 2) | ((hh >> 1) & 3);
    int k16 = hh >> 4;
    int reg = (((hh >> 3) & 1) << 1) | r8;
    return ((((wm << 6) | k16) * 2 + mt) * 32 + lane) * 8 + reg * 2 + (hh & 1);
}

// ---------------- init: encoder state -> packed h buffers + c ----------------
__global__ void init_pack_kernel(const float* __restrict__ eh, const float* __restrict__ ec) {
    int i = blockIdx.x * blockDim.x + threadIdx.x;
    if (i < B_ * HDIM) {
        int b = i >> 10, hh = i & 1023;
        ((__half*)g_h0p)[65536 + hp_idx(b, hh)] = __float2half_rn(eh[i]);
        ((__half*)g_h1p)[65536 + hp_idx(b, hh)] = __float2half_rn(eh[B_ * HDIM + i]);
        g_c0[i] = ec[i];
        g_c1[i] = ec[B_ * HDIM + i];
    }
}

// ---------------- bias1 fold ----------------
__global__ void bias1_kernel(const float* __restrict__ b_ih1, const float* __restrict__ b_hh1) {
    int i = blockIdx.x * blockDim.x + threadIdx.x;
    if (i < GDIM) g_bias1[i] = b_ih1[i] + b_hh1[i];
}

// ---------------- fp16 weight pre-pack into mma fragment order ----------------
// hot-loop index: mat*524288 + n32*4096 + k16*64 + half*32 + lane
__global__ void pack_w_kernel(const float* __restrict__ W0, const float* __restrict__ W1,
                              const float* __restrict__ W2) {
    int g = blockIdx.x * 256 + threadIdx.x;   // 1,572,864 total
    int lane = g & 31;
    int hf   = (g >> 5) & 1;
    int k16  = (g >> 6) & 63;
    int n32  = (g >> 12) & 127;
    int mat  = g >> 19;
    const float* W = (mat == 0) ? W0 : ((mat == 1) ? W1 : W2);
    int bxm = n32 >> 1, wn = n32 & 1;
    int n0 = wn * 32 + hf * 16 + (lane >> 2);
    int n1 = n0 + 8;
    // quadrant-gathered column map: j = (n>>4)*1024 + bxm*16 + (n&15)
    int j0 = ((n0 >> 4) << 10) + (bxm << 4) + (n0 & 15);
    int j1 = ((n1 >> 4) << 10) + (bxm << 4) + (n1 & 15);
    int k0 = k16 * 16 + 2 * (lane & 3);
    const float* r0 = W + (size_t)j0 * HDIM + k0;
    const float* r1 = W + (size_t)j1 * HDIM + k0;
    uint4 v;
    v.x = pkh(r0[0], r0[1]);  v.y = pkh(r0[8], r0[9]);
    v.z = pkh(r1[0], r1[1]);  v.w = pkh(r1[8], r1[9]);
    g_wph[g] = v;
}

// ---------------- pre0: biases + static part of layer-0 gates ----------------
// one block per j; 256 threads: b = t>>2, kq = t&3, 256-k slab each; smem reduce
__global__ void __launch_bounds__(256) pre0_kernel(
    const float* __restrict__ enc_outs, const int* __restrict__ langs,
    const float* __restrict__ embed, const float* __restrict__ W_ih0,
    const float* __restrict__ b_ih0, const float* __restrict__ b_hh0)
{
    __shared__ float red[256];
    const int j = blockIdx.x;
    const int t = threadIdx.x;
    const int b = t >> 2, kq = t & 3;
    const float* Wrow = W_ih0 + (size_t)j * IN0 + 512;
    const int lang = langs[b];
    const int k0 = kq * 256;
    float acc = 0.0f;
    if (kq < 2) {
        const float* src = enc_outs + (b * 128 + 127) * 512 + k0;
        #pragma unroll 8
        for (int kk = 0; kk < 256; kk++) acc += src[kk] * Wrow[k0 + kk];
    } else {
        const float* src = embed + (size_t)lang * EDIM + (k0 - 512);
        #pragma unroll 8
        for (int kk = 0; kk < 256; kk++) acc += src[kk] * Wrow[k0 + kk];
    }
    red[t] = acc;
    __syncthreads();
    if (kq == 0) {
        float s = red[t] + red[t + 1] + red[t + 2] + red[t + 3];
        g_pre0[b * GDIM + j] = s + b_ih0[j] + b_hh0[j];
    }
}

// ---------------- xw: big precompute GEMM in fp16 (+ pre0 folded at store) ----------------
// g_xw[t][b][j] = sum_{k<512} embed[tok(b,t)][k] * W_ih0[j][k]; CTA tile 128(M) x 64(N)
__global__ void __launch_bounds__(256) xw_kernel(
    const int* __restrict__ prev, const float* __restrict__ embed,
    const float* __restrict__ W_ih0)
{
    __shared__ unsigned As[128][20];   // f16x2 pairs, k32 chunk = 16 pairs + pad
    __shared__ unsigned Bs[64][20];
    __shared__ int toks[128];
    const int tid = threadIdx.x, lane = tid & 31, warp = tid >> 5;
    const int wm = warp >> 1, wn = warp & 1;   // 4 x 2 warps, warp tile 32x32
    const int bx = blockIdx.x;                 // N tile (64 cols)
    const int by = blockIdx.y;                 // M tile (128 rows)

    if (tid < 128) {
        int r = by * 128 + tid;
        toks[tid] = prev[(r & 63) * SLEN + (r >> 6)];
    }
    __syncthreads();

    float acc[2][4][4];
    #pragma unroll
    for (int i = 0; i < 2; i++)
        #pragma unroll
        for (int jj = 0; jj < 4; jj++)
            #pragma unroll
            for (int k = 0; k < 4; k++) acc[i][jj][k] = 0.0f;

    for (int k0 = 0; k0 < EDIM; k0 += 32) {
        #pragma unroll
        for (int r = 0; r < 4; r++) {          // A: 128 rows x 8 float4
            int idx = tid + r * 256;
            int row = idx >> 3, c4 = idx & 7;
            float4 v = *(const float4*)(embed + (size_t)toks[row] * EDIM + k0 + c4 * 4);
            As[row][c4 * 2]     = pkh(v.x, v.y);
            As[row][c4 * 2 + 1] = pkh(v.z, v.w);
        }
        #pragma unroll
        for (int r = 0; r < 2; r++) {          // B: 64 rows x 8 float4
            int idx = tid + r * 256;
            int n = idx >> 3, c4 = idx & 7;
            int j = bx * 64 + n;
            float4 v = *(const float4*)(W_ih0 + (size_t)j * IN0 + k0 + c4 * 4);
            Bs[n][c4 * 2]     = pkh(v.x, v.y);
            Bs[n][c4 * 2 + 1] = pkh(v.z, v.w);
        }
        __syncthreads();
        #pragma unroll
        for (int kc = 0; kc < 2; kc++) {       // two k16 mma steps per k32 chunk
            const int kp = kc * 8 + (lane & 3);
            unsigned a[2][4], b[4][2];
            #pragma unroll
            for (int mt = 0; mt < 2; mt++) {
                int r0 = wm * 32 + mt * 16 + (lane >> 2);
                a[mt][0] = As[r0][kp];     a[mt][1] = As[r0 + 8][kp];
                a[mt][2] = As[r0][kp + 4]; a[mt][3] = As[r0 + 8][kp + 4];
            }
            #pragma unroll
            for (int nt = 0; nt < 4; nt++) {
                int n0 = wn * 32 + nt * 8 + (lane >> 2);
                b[nt][0] = Bs[n0][kp]; b[nt][1] = Bs[n0][kp + 4];
            }
            #pragma unroll
            for (int mt = 0; mt < 2; mt++)
                #pragma unroll
                for (int nt = 0; nt < 4; nt++)
                    mma16(acc[mt][nt], a[mt], b[nt]);
        }
        __syncthreads();
    }
    #pragma unroll
    for (int mt = 0; mt < 2; mt++)
        #pragma unroll
        for (int nt = 0; nt < 4; nt++) {
            int row = wm * 32 + mt * 16 + (lane >> 2);
            int col = bx * 64 + wn * 32 + nt * 8 + 2 * (lane & 3);
            int rg0 = by * 128 + row;
            int rg1 = rg0 + 8;
            size_t base0 = (size_t)rg0 * GDIM + col;
            size_t base1 = (size_t)rg1 * GDIM + col;
            const float* p0 = g_pre0 + (rg0 & 63) * GDIM + col;
            const float* p1 = g_pre0 + (rg1 & 63) * GDIM + col;
            *(float2*)(g_xw + base0) = make_float2(acc[mt][nt][0] + p0[0], acc[mt][nt][1] + p0[1]);
            *(float2*)(g_xw + base1) = make_float2(acc[mt][nt][2] + p1[0], acc[mt][nt][3] + p1[1]);
        }
}

// ---------------- grid-wide barrier (all 128 CTAs co-resident) ----------------
__device__ __forceinline__ void grid_sync() {
    __syncthreads();
    if (threadIdx.x == 0) {
        unsigned gen = g_bar_gen;
        __threadfence();
        if (atomicAdd((unsigned*)&g_bar_cnt, 1u) == 127u) {
            g_bar_cnt = 0;
            __threadfence();
            g_bar_gen = gen + 1;
        } else {
            while (g_bar_gen == gen) { __nanosleep(16); }
        }
        __threadfence();
    }
    __syncthreads();
}

// ---------------- cp.async producer: one k16 stage = 512 uint4 (8KB) ----------------
// SMEM stage layout (uint4):
//   A at [0..255]:   wk*128 + wm*64 + mt*32 + lane
//   W at [256..511]: 256 + wk*128 + wn*64 + half*32 + lane
__device__ __forceinline__ void produce_stage(uint4* sbuf, int s, bool isl0, int cx,
                                              int pa, int pb) {
    const int tid = threadIdx.x;
    #pragma unroll
    for (int o = 0; o < 2; o++) {
        int id = o * 256 + tid;
        int lane = id & 31;
        int q   = (id >> 5) & 1;   // mt for A, half for W
        int sel = (id >> 6) & 1;   // wm for A, wn for W
        int wk  = (id >> 7) & 1;
        bool isA = id < 256;
        const uint4* src;
        if (isA) {
            const uint4* hp;
            int k16;
            if (isl0) { hp = g_h0p + pa * 8192; k16 = wk * 32 + s; }
            else      { hp = (wk == 0 ? g_h0p + pa * 8192 : g_h1p + pb * 8192); k16 = s; }
            src = hp + sel * 4096 + k16 * 64 + q * 32 + lane;
        } else {
            int mat, k16;
            if (isl0) { mat = 0; k16 = wk * 32 + s; }
            else      { mat = 1 + wk; k16 = s; }
            src = g_wph + mat * 524288 + (cx * 2 + sel) * 4096 + k16 * 64 + q * 32 + lane;
        }
        unsigned saddr;
        asm("{ .reg .u64 t; cvta.to.shared.u64 t, %1; cvt.u32.u64 %0, t; }"
            : "=r"(saddr) : "l"(sbuf + id));
        asm volatile("cp.async.cg.shared.global [%0], [%1], 16;\n"
                     :: "r"(saddr), "l"(src));
    }
}

// ---------------- persistent LSTM kernel ----------------
// CTAs 0..63: layer0 step t=i.  CTAs 64..127: layer1 step t=i-1.  One barrier/iter.
// 8 warps: wn = w&1, wm = (w>>1)&1, wk = w>>2 (split-K half / matrix select).
// Mainloop consumes TWO k16 stages per wait+sync (halves barrier count vs round-6).
__global__ void __launch_bounds__(256, 1) persist_kernel(float* __restrict__ out) {
    extern __shared__ uint4 dynsmem[];
    uint4* stg = dynsmem;                           // DEPTH * 512 uint4 = 64KB
    float* gs  = (float*)(dynsmem + DEPTH * 512);   // 64*68 floats

    const int tid = threadIdx.x, lane = tid & 31, warp = tid >> 5;
    const int wn = warp & 1, wm = (warp >> 1) & 1, wk = warp >> 2;
    const int bx = blockIdx.x;
    const bool isl0 = bx < 64;
    const int cx = isl0 ? bx : bx - 64;
    const int NS = isl0 ? 32 : 64;

    for (int i = 0; i <= 256; i++) {
        const int pa = (i + 1) & 1;
        const int pb = i & 1;
        const bool active = isl0 ? (i < 256) : (i >= 1);
        if (active) {
            const int t = isl0 ? i : i - 1;
            float acc[2][4][4];
            #pragma unroll
            for (int a = 0; a < 2; a++)
                #pragma unroll
                for (int b = 0; b < 4; b++)
                    #pragma unroll
                    for (int c = 0; c < 4; c++) acc[a][b][c] = 0.0f;

            // pipeline prologue: 6 stages in flight
            #pragma unroll
            for (int s = 0; s < 6; s++) {
                produce_stage(stg + s * 512, s, isl0, cx, pa, pb);
                asm volatile("cp.async.commit_group;\n");
            }

            for (int c = 0; c < NS; c += 2) {
                // stages c, c+1 must be complete:
                // allowed pending = min(4, NS - c - 2)
                if (c + 6 <= NS)      asm volatile("cp.async.wait_group 4;\n");
                else if (c + 4 <= NS) asm volatile("cp.async.wait_group 2;\n");
                else                  asm volatile("cp.async.wait_group 0;\n");
                __syncthreads();
                #pragma unroll
                for (int jj = 0; jj < 2; jj++) {
                    const uint4* sb = stg + ((c + jj) & (DEPTH - 1)) * 512;
                    const uint4* Ac = sb + wk * 128 + wm * 64;
                    const uint4* Wc = sb + 256 + wk * 128 + wn * 64;
                    uint4 w0 = Wc[lane], w1 = Wc[32 + lane];
                    unsigned B0[2] = {w0.x, w0.y}, B1[2] = {w0.z, w0.w};
                    unsigned B2[2] = {w1.x, w1.y}, B3[2] = {w1.z, w1.w};
                    uint4 a0 = Ac[lane], a1 = Ac[32 + lane];
                    unsigned A0[4] = {a0.x, a0.y, a0.z, a0.w};
                    unsigned A1[4] = {a1.x, a1.y, a1.z, a1.w};
                    mma16(acc[0][0], A0, B0); mma16(acc[0][1], A0, B1);
                    mma16(acc[0][2], A0, B2); mma16(acc[0][3], A0, B3);
                    mma16(acc[1][0], A1, B0); mma16(acc[1][1], A1, B1);
                    mma16(acc[1][2], A1, B2); mma16(acc[1][3], A1, B3);
                }
                if (c + 6 < NS) {
                    produce_stage(stg + ((c + 6) & (DEPTH - 1)) * 512, c + 6, isl0, cx, pa, pb);
                    asm volatile("cp.async.commit_group;\n");
                }
                if (c + 7 < NS) {
                    produce_stage(stg + ((c + 7) & (DEPTH - 1)) * 512, c + 7, isl0, cx, pa, pb);
                    asm volatile("cp.async.commit_group;\n");
                }
            }

            // split-K reduce via smem: wk=1 stores, wk=0 adds
            if (wk == 1) {
                #pragma unroll
                for (int mt = 0; mt < 2; mt++)
                    #pragma unroll
                    for (int nt = 0; nt < 4; nt++) {
                        int row = wm * 32 + mt * 16 + (lane >> 2);
                        int col = wn * 32 + nt * 8 + 2 * (lane & 3);
                        gs[row * 68 + col]       = acc[mt][nt][0];
                        gs[row * 68 + col + 1]   = acc[mt][nt][1];
                        gs[(row + 8) * 68 + col]     = acc[mt][nt][2];
                        gs[(row + 8) * 68 + col + 1] = acc[mt][nt][3];
                    }
            }
            __syncthreads();
            if (wk == 0) {
                #pragma unroll
                for (int mt = 0; mt < 2; mt++)
                    #pragma unroll
                    for (int nt = 0; nt < 4; nt++) {
                        int row = wm * 32 + mt * 16 + (lane >> 2);
                        int col = wn * 32 + nt * 8 + 2 * (lane & 3);
                        gs[row * 68 + col]       += acc[mt][nt][0];
                        gs[row * 68 + col + 1]   += acc[mt][nt][1];
                        gs[(row + 8) * 68 + col]     += acc[mt][nt][2];
                        gs[(row + 8) * 68 + col + 1] += acc[mt][nt][3];
                    }
            }
            __syncthreads();

            __half* hp_out = isl0 ? ((__half*)g_h0p + pb * 65536)
                                  : ((__half*)g_h1p + pa * 65536);
            const float* xw_t = g_xw + (size_t)t * (B_ * GDIM);
            float* cc = isl0 ? g_c0 : g_c1;

            #pragma unroll
            for (int ee = 0; ee < 4; ee++) {
                int e = tid + ee * 256;
                int b = e >> 4, u = e & 15;
                int hh = (cx << 4) + u;
                float g0, g1, g2, g3;
                if (isl0) {
                    g0 = gs[b * 68 + u]      + xw_t[b * GDIM + hh];
                    g1 = gs[b * 68 + 16 + u] + xw_t[b * GDIM + 1024 + hh];
                    g2 = gs[b * 68 + 32 + u] + xw_t[b * GDIM + 2048 + hh];
                    g3 = gs[b * 68 + 48 + u] + xw_t[b * GDIM + 3072 + hh];
                } else {
                    g0 = gs[b * 68 + u]      + g_bias1[hh];
                    g1 = gs[b * 68 + 16 + u] + g_bias1[1024 + hh];
                    g2 = gs[b * 68 + 32 + u] + g_bias1[2048 + hh];
                    g3 = gs[b * 68 + 48 + u] + g_bias1[3072 + hh];
                }
                float ci = cc[b * HDIM + hh];
                float cn = sigm(g1) * ci + sigm(g0) * tanhf(g2);
                cc[b * HDIM + hh] = cn;
                float hn = sigm(g3) * tanhf(cn);
                hp_out[hp_idx(b, hh)] = __float2half_rn(hn);
                if (!isl0) out[(size_t)t * (B_ * HDIM) + b * HDIM + hh] = hn;
            }
        }
        grid_sync();
    }
}

// ---------------- launch ----------------
extern "C" void kernel_launch(void* const* d_in, const int* in_sizes, int n_in,
                              void* d_out, int out_size) {
    const int*   prev   = (const int*)d_in[0];
    const int*   langs  = (const int*)d_in[1];
    const float* enc_o  = (const float*)d_in[2];
    const float* enc_h  = (const float*)d_in[3];
    const float* enc_c  = (const float*)d_in[4];
    const float* embed  = (const float*)d_in[5];
    const float* W_ih0  = (const float*)d_in[6];
    const float* W_hh0  = (const float*)d_in[7];
    const float* b_ih0  = (const float*)d_in[8];
    const float* b_hh0  = (const float*)d_in[9];
    const float* W_ih1  = (const float*)d_in[10];
    const float* W_hh1  = (const float*)d_in[11];
    const float* b_ih1  = (const float*)d_in[12];
    const float* b_hh1  = (const float*)d_in[13];
    float* out = (float*)d_out;

    const int smem_bytes = DEPTH * 512 * 16 + 64 * 68 * 4;   // 64KB + 17.4KB
    static int attr_done = 0;
    if (!attr_done) {
        cudaFuncSetAttribute(persist_kernel, cudaFuncAttributeMaxDynamicSharedMemorySize,
                             smem_bytes);
        attr_done = 1;
    }

    init_pack_kernel<<<256, 256>>>(enc_h, enc_c);
    bias1_kernel<<<16, 256>>>(b_ih1, b_hh1);
    pack_w_kernel<<<6144, 256>>>(W_hh0, W_ih1, W_hh1);
    pre0_kernel<<<GDIM, 256>>>(enc_o, langs, embed, W_ih0, b_ih0, b_hh0);
    xw_kernel<<<dim3(GDIM / 64, (SLEN * B_) / 128), 256>>>(prev, embed, W_ih0);

    persist_kernel<<<128, 256, smem_bytes>>>(out);
}

// round 12
// speedup vs baseline: 2.0297x; 1.1772x over previous
#include <cuda_runtime.h>
#include <cuda_bf16.h>
#include <cuda_fp16.h>
#include <math.h>

// Problem dims
#define B_    64
#define HDIM  1024
#define SLEN  256
#define GDIM  4096      // 4*H
#define EDIM  512
#define IN0   1536

#define DEPTH 12        // cp.async ring buffers (k16 granularity, 8KB each), 3 groups of 4

// ---------------- device scratch (no allocs allowed) ----------------
__device__ float g_xw[67108864];        // [S][B][4H] (268MB): xw + pre0 folded in
__device__ float g_pre0[B_ * GDIM];     // static-part gate precompute (incl. biases l0)
__device__ float g_bias1[GDIM];         // b_ih1 + b_hh1
__device__ uint4 g_wph[1572864];        // fp16 packed weights: [mat(3)][n32(128)][k16(64)][half(2)][lane(32)] (24MB)
__device__ uint4 g_h0p[16384];          // fp16 packed h0 ping-pong: [slot(2)][wm(2)][k16(64)][mt(2)][lane(32)]
__device__ uint4 g_h1p[16384];          // fp16 packed h1 ping-pong
__device__ float g_c0[B_ * HDIM];
__device__ float g_c1[B_ * HDIM];

// grid barrier state
__device__ volatile unsigned g_bar_cnt;
__device__ volatile unsigned g_bar_gen;

// ---------------- helpers ----------------
__device__ __forceinline__ unsigned pkh(float a, float b) {
    __half2 h = __halves2half2(__float2half_rn(a), __float2half_rn(b));
    return *(unsigned*)&h;
}

// fp16 m16n8k16, f32 accumulate
__device__ __forceinline__ void mma16(float d[4], const unsigned a[4], const unsigned b[2]) {
    asm volatile(
        "mma.sync.aligned.m16n8k16.row.col.f32.f16.f16.f32 "
        "{%0,%1,%2,%3}, {%4,%5,%6,%7}, {%8,%9}, {%0,%1,%2,%3};\n"
        : "+f"(d[0]), "+f"(d[1]), "+f"(d[2]), "+f"(d[3])
        : "r"(a[0]), "r"(a[1]), "r"(a[2]), "r"(a[3]), "r"(b[0]), "r"(b[1]));
}

__device__ __forceinline__ float sigm(float x) { return 1.0f / (1.0f + __expf(-x)); }

// packed-h half index within one slot (65536 halves per slot)
// uint4 layout: [wm(2)][k16(64)][mt(2)][lane(32)], uint4 = {a0,a1,a2,a3} f16x2 regs
__device__ __forceinline__ int hp_idx(int b, int hh) {
    int wm = b >> 5;
    int mt = (b >> 4) & 1;
    int r8 = (b >> 3) & 1;
    int lane = ((b & 7) << 2) | ((hh >> 1) & 3);
    int k16 = hh >> 4;
    int reg = (((hh >> 3) & 1) << 1) | r8;
    return ((((wm << 6) | k16) * 2 + mt) * 32 + lane) * 8 + reg * 2 + (hh & 1);
}

// ---------------- merged setup: pack_w + init_pack + bias1 (one launch) ----------------
// grid covers pack_w (1,572,864 threads); smaller jobs branch off the same index.
__global__ void __launch_bounds__(256) setup_kernel(
    const float* __restrict__ eh, const float* __restrict__ ec,
    const float* __restrict__ b_ih1, const float* __restrict__ b_hh1,
    const float* __restrict__ W0, const float* __restrict__ W1,
    const float* __restrict__ W2)
{
    int g = blockIdx.x * 256 + threadIdx.x;   // 1,572,864 total

    // ---- fp16 weight pre-pack: hot-loop index mat*524288 + n32*4096 + k16*64 + half*32 + lane
    {
        int lane = g & 31;
        int hf   = (g >> 5) & 1;
        int k16  = (g >> 6) & 63;
        int n32  = (g >> 12) & 127;
        int mat  = g >> 19;
        const float* W = (mat == 0) ? W0 : ((mat == 1) ? W1 : W2);
        int bxm = n32 >> 1, wn = n32 & 1;
        int n0 = wn * 32 + hf * 16 + (lane >> 2);
        int n1 = n0 + 8;
        // quadrant-gathered column map: j = (n>>4)*1024 + bxm*16 + (n&15)
        int j0 = ((n0 >> 4) << 10) + (bxm << 4) + (n0 & 15);
        int j1 = ((n1 >> 4) << 10) + (bxm << 4) + (n1 & 15);
        int k0 = k16 * 16 + 2 * (lane & 3);
        const float* r0 = W + (size_t)j0 * HDIM + k0;
        const float* r1 = W + (size_t)j1 * HDIM + k0;
        uint4 v;
        v.x = pkh(r0[0], r0[1]);  v.y = pkh(r0[8], r0[9]);
        v.z = pkh(r1[0], r1[1]);  v.w = pkh(r1[8], r1[9]);
        g_wph[g] = v;
    }

    // ---- encoder state -> packed h buffers + c
    if (g < B_ * HDIM) {
        int b = g >> 10, hh = g & 1023;
        ((__half*)g_h0p)[65536 + hp_idx(b, hh)] = __float2half_rn(eh[g]);
        ((__half*)g_h1p)[65536 + hp_idx(b, hh)] = __float2half_rn(eh[B_ * HDIM + g]);
        g_c0[g] = ec[g];
        g_c1[g] = ec[B_ * HDIM + g];
    }

    // ---- bias1 fold
    if (g < GDIM) g_bias1[g] = b_ih1[g] + b_hh1[g];
}

// ---------------- pre0: biases + static part of layer-0 gates ----------------
// one block per j; 256 threads: b = t>>2, kq = t&3, 256-k slab each; smem reduce
__global__ void __launch_bounds__(256) pre0_kernel(
    const float* __restrict__ enc_outs, const int* __restrict__ langs,
    const float* __restrict__ embed, const float* __restrict__ W_ih0,
    const float* __restrict__ b_ih0, const float* __restrict__ b_hh0)
{
    __shared__ float red[256];
    const int j = blockIdx.x;
    const int t = threadIdx.x;
    const int b = t >> 2, kq = t & 3;
    const float* Wrow = W_ih0 + (size_t)j * IN0 + 512;
    const int lang = langs[b];
    const int k0 = kq * 256;
    float acc = 0.0f;
    if (kq < 2) {
        const float* src = enc_outs + (b * 128 + 127) * 512 + k0;
        #pragma unroll 8
        for (int kk = 0; kk < 256; kk++) acc += src[kk] * Wrow[k0 + kk];
    } else {
        const float* src = embed + (size_t)lang * EDIM + (k0 - 512);
        #pragma unroll 8
        for (int kk = 0; kk < 256; kk++) acc += src[kk] * Wrow[k0 + kk];
    }
    red[t] = acc;
    __syncthreads();
    if (kq == 0) {
        float s = red[t] + red[t + 1] + red[t + 2] + red[t + 3];
        g_pre0[b * GDIM + j] = s + b_ih0[j] + b_hh0[j];
    }
}

// ---------------- xw: big precompute GEMM in fp16 (+ pre0 folded at store) ----------------
// g_xw[t][b][j] = sum_{k<512} embed[tok(b,t)][k] * W_ih0[j][k]; CTA tile 128(M) x 64(N)
__global__ void __launch_bounds__(256) xw_kernel(
    const int* __restrict__ prev, const float* __restrict__ embed,
    const float* __restrict__ W_ih0)
{
    __shared__ unsigned As[128][20];   // f16x2 pairs, k32 chunk = 16 pairs + pad
    __shared__ unsigned Bs[64][20];
    __shared__ int toks[128];
    const int tid = threadIdx.x, lane = tid & 31, warp = tid >> 5;
    const int wm = warp >> 1, wn = warp & 1;   // 4 x 2 warps, warp tile 32x32
    const int bx = blockIdx.x;                 // N tile (64 cols)
    const int by = blockIdx.y;                 // M tile (128 rows)

    if (tid < 128) {
        int r = by * 128 + tid;
        toks[tid] = prev[(r & 63) * SLEN + (r >> 6)];
    }
    __syncthreads();

    float acc[2][4][4];
    #pragma unroll
    for (int i = 0; i < 2; i++)
        #pragma unroll
        for (int jj = 0; jj < 4; jj++)
            #pragma unroll
            for (int k = 0; k < 4; k++) acc[i][jj][k] = 0.0f;

    for (int k0 = 0; k0 < EDIM; k0 += 32) {
        #pragma unroll
        for (int r = 0; r < 4; r++) {          // A: 128 rows x 8 float4
            int idx = tid + r * 256;
            int row = idx >> 3, c4 = idx & 7;
            float4 v = *(const float4*)(embed + (size_t)toks[row] * EDIM + k0 + c4 * 4);
            As[row][c4 * 2]     = pkh(v.x, v.y);
            As[row][c4 * 2 + 1] = pkh(v.z, v.w);
        }
        #pragma unroll
        for (int r = 0; r < 2; r++) {          // B: 64 rows x 8 float4
            int idx = tid + r * 256;
            int n = idx >> 3, c4 = idx & 7;
            int j = bx * 64 + n;
            float4 v = *(const float4*)(W_ih0 + (size_t)j * IN0 + k0 + c4 * 4);
            Bs[n][c4 * 2]     = pkh(v.x, v.y);
            Bs[n][c4 * 2 + 1] = pkh(v.z, v.w);
        }
        __syncthreads();
        #pragma unroll
        for (int kc = 0; kc < 2; kc++) {       // two k16 mma steps per k32 chunk
            const int kp = kc * 8 + (lane & 3);
            unsigned a[2][4], b[4][2];
            #pragma unroll
            for (int mt = 0; mt < 2; mt++) {
                int r0 = wm * 32 + mt * 16 + (lane >> 2);
                a[mt][0] = As[r0][kp];     a[mt][1] = As[r0 + 8][kp];
                a[mt][2] = As[r0][kp + 4]; a[mt][3] = As[r0 + 8][kp + 4];
            }
            #pragma unroll
            for (int nt = 0; nt < 4; nt++) {
                int n0 = wn * 32 + nt * 8 + (lane >> 2);
                b[nt][0] = Bs[n0][kp]; b[nt][1] = Bs[n0][kp + 4];
            }
            #pragma unroll
            for (int mt = 0; mt < 2; mt++)
                #pragma unroll
                for (int nt = 0; nt < 4; nt++)
                    mma16(acc[mt][nt], a[mt], b[nt]);
        }
        __syncthreads();
    }
    #pragma unroll
    for (int mt = 0; mt < 2; mt++)
        #pragma unroll
        for (int nt = 0; nt < 4; nt++) {
            int row = wm * 32 + mt * 16 + (lane >> 2);
            int col = bx * 64 + wn * 32 + nt * 8 + 2 * (lane & 3);
            int rg0 = by * 128 + row;
            int rg1 = rg0 + 8;
            size_t base0 = (size_t)rg0 * GDIM + col;
            size_t base1 = (size_t)rg1 * GDIM + col;
            const float* p0 = g_pre0 + (rg0 & 63) * GDIM + col;
            const float* p1 = g_pre0 + (rg1 & 63) * GDIM + col;
            *(float2*)(g_xw + base0) = make_float2(acc[mt][nt][0] + p0[0], acc[mt][nt][1] + p0[1]);
            *(float2*)(g_xw + base1) = make_float2(acc[mt][nt][2] + p1[0], acc[mt][nt][3] + p1[1]);
        }
}

// ---------------- grid-wide barrier (all 128 CTAs co-resident) ----------------
__device__ __forceinline__ void grid_sync() {
    __syncthreads();
    if (threadIdx.x == 0) {
        unsigned gen = g_bar_gen;
        __threadfence();
        if (atomicAdd((unsigned*)&g_bar_cnt, 1u) == 127u) {
            g_bar_cnt = 0;
            __threadfence();
            g_bar_gen = gen + 1;
        } else {
            while (g_bar_gen == gen) { __nanosleep(16); }
        }
        __threadfence();
    }
    __syncthreads();
}

// ---------------- cp.async producer: one k16 stage = 512 uint4 (8KB) ----------------
// SMEM stage layout (uint4):
//   A at [0..255]:   wk*128 + wm*64 + mt*32 + lane
//   W at [256..511]: 256 + wk*128 + wn*64 + half*32 + lane
__device__ __forceinline__ void produce_stage(uint4* sbuf, int s, bool isl0, int cx,
                                              int pa, int pb) {
    const int tid = threadIdx.x;
    #pragma unroll
    for (int o = 0; o < 2; o++) {
        int id = o * 256 + tid;
        int lane = id & 31;
        int q   = (id >> 5) & 1;   // mt for A, half for W
        int sel = (id >> 6) & 1;   // wm for A, wn for W
        int wk  = (id >> 7) & 1;
        bool isA = id < 256;
        const uint4* src;
        if (isA) {
            const uint4* hp;
            int k16;
            if (isl0) { hp = g_h0p + pa * 8192; k16 = wk * 32 + s; }
            else      { hp = (wk == 0 ? g_h0p + pa * 8192 : g_h1p + pb * 8192); k16 = s; }
            src = hp + sel * 4096 + k16 * 64 + q * 32 + lane;
        } else {
            int mat, k16;
            if (isl0) { mat = 0; k16 = wk * 32 + s; }
            else      { mat = 1 + wk; k16 = s; }
            src = g_wph + mat * 524288 + (cx * 2 + sel) * 4096 + k16 * 64 + q * 32 + lane;
        }
        unsigned saddr;
        asm("{ .reg .u64 t; cvta.to.shared.u64 t, %1; cvt.u32.u64 %0, t; }"
            : "=r"(saddr) : "l"(sbuf + id));
        asm volatile("cp.async.cg.shared.global [%0], [%1], 16;\n"
                     :: "r"(saddr), "l"(src));
    }
}

// ---------------- persistent LSTM kernel ----------------
// CTAs 0..63: layer0 step t=i.  CTAs 64..127: layer1 step t=i-1.  One barrier/iter.
// 8 warps: wn = w&1, wm = (w>>1)&1, wk = w>>2 (split-K half / matrix select).
// Mainloop consumes FOUR k16 stages per wait+sync; DEPTH=12 (3 groups of 4).
__global__ void __launch_bounds__(256, 1) persist_kernel(float* __restrict__ out) {
    extern __shared__ uint4 dynsmem[];
    uint4* stg = dynsmem;                           // DEPTH * 512 uint4 = 96KB
    float* gs  = (float*)(dynsmem + DEPTH * 512);   // 64*68 floats

    const int tid = threadIdx.x, lane = tid & 31, warp = tid >> 5;
    const int wn = warp & 1, wm = (warp >> 1) & 1, wk = warp >> 2;
    const int bx = blockIdx.x;
    const bool isl0 = bx < 64;
    const int cx = isl0 ? bx : bx - 64;
    const int NS = isl0 ? 32 : 64;

    for (int i = 0; i <= 256; i++) {
        const int pa = (i + 1) & 1;
        const int pb = i & 1;
        const bool active = isl0 ? (i < 256) : (i >= 1);
        if (active) {
            const int t = isl0 ? i : i - 1;
            float acc[2][4][4];
            #pragma unroll
            for (int a = 0; a < 2; a++)
                #pragma unroll
                for (int b = 0; b < 4; b++)
                    #pragma unroll
                    for (int c = 0; c < 4; c++) acc[a][b][c] = 0.0f;

            // prologue: 2 groups of 4 stages
            #pragma unroll
            for (int s = 0; s < 4; s++) produce_stage(stg + s * 512, s, isl0, cx, pa, pb);
            asm volatile("cp.async.commit_group;\n");
            #pragma unroll
            for (int s = 4; s < 8; s++) produce_stage(stg + s * 512, s, isl0, cx, pa, pb);
            asm volatile("cp.async.commit_group;\n");

            for (int c = 0; c < NS; c += 4) {
                if (c + 4 < NS) asm volatile("cp.async.wait_group 1;\n");
                else            asm volatile("cp.async.wait_group 0;\n");
                __syncthreads();
                const int cb = (c >> 2) % 3;              // consume group 0..2
                const uint4* gb = stg + cb * 2048;
                #pragma unroll
                for (int jj = 0; jj < 4; jj++) {
                    const uint4* sb = gb + jj * 512;
                    const uint4* Ac = sb + wk * 128 + wm * 64;
                    const uint4* Wc = sb + 256 + wk * 128 + wn * 64;
                    uint4 w0 = Wc[lane], w1 = Wc[32 + lane];
                    unsigned B0[2] = {w0.x, w0.y}, B1[2] = {w0.z, w0.w};
                    unsigned B2[2] = {w1.x, w1.y}, B3[2] = {w1.z, w1.w};
                    uint4 a0 = Ac[lane], a1 = Ac[32 + lane];
                    unsigned A0[4] = {a0.x, a0.y, a0.z, a0.w};
                    unsigned A1[4] = {a1.x, a1.y, a1.z, a1.w};
                    mma16(acc[0][0], A0, B0); mma16(acc[0][1], A0, B1);
                    mma16(acc[0][2], A0, B2); mma16(acc[0][3], A0, B3);
                    mma16(acc[1][0], A1, B0); mma16(acc[1][1], A1, B1);
                    mma16(acc[1][2], A1, B2); mma16(acc[1][3], A1, B3);
                }
                if (c + 8 < NS) {
                    const int pbuf = (cb + 2) % 3;        // produce group (2 ahead)
                    uint4* pg = stg + pbuf * 2048;
                    #pragma unroll
                    for (int s = 0; s < 4; s++)
                        produce_stage(pg + s * 512, c + 8 + s, isl0, cx, pa, pb);
                    asm volatile("cp.async.commit_group;\n");
                }
            }

            // split-K reduce via smem: wk=1 stores, wk=0 adds
            __syncthreads();
            if (wk == 1) {
                #pragma unroll
                for (int mt = 0; mt < 2; mt++)
                    #pragma unroll
                    for (int nt = 0; nt < 4; nt++) {
                        int row = wm * 32 + mt * 16 + (lane >> 2);
                        int col = wn * 32 + nt * 8 + 2 * (lane & 3);
                        gs[row * 68 + col]       = acc[mt][nt][0];
                        gs[row * 68 + col + 1]   = acc[mt][nt][1];
                        gs[(row + 8) * 68 + col]     = acc[mt][nt][2];
                        gs[(row + 8) * 68 + col + 1] = acc[mt][nt][3];
                    }
            }
            __syncthreads();
            if (wk == 0) {
                #pragma unroll
                for (int mt = 0; mt < 2; mt++)
                    #pragma unroll
                    for (int nt = 0; nt < 4; nt++) {
                        int row = wm * 32 + mt * 16 + (lane >> 2);
                        int col = wn * 32 + nt * 8 + 2 * (lane & 3);
                        gs[row * 68 + col]       += acc[mt][nt][0];
                        gs[row * 68 + col + 1]   += acc[mt][nt][1];
                        gs[(row + 8) * 68 + col]     += acc[mt][nt][2];
                        gs[(row + 8) * 68 + col + 1] += acc[mt][nt][3];
                    }
            }
            __syncthreads();

            __half* hp_out = isl0 ? ((__half*)g_h0p + pb * 65536)
                                  : ((__half*)g_h1p + pa * 65536);
            const float* xw_t = g_xw + (size_t)t * (B_ * GDIM);
            float* cc = isl0 ? g_c0 : g_c1;

            #pragma unroll
            for (int ee = 0; ee < 4; ee++) {
                int e = tid + ee * 256;
                int b = e >> 4, u = e & 15;
                int hh = (cx << 4) + u;
                float g0, g1, g2, g3;
                if (isl0) {
                    g0 = gs[b * 68 + u]      + xw_t[b * GDIM + hh];
                    g1 = gs[b * 68 + 16 + u] + xw_t[b * GDIM + 1024 + hh];
                    g2 = gs[b * 68 + 32 + u] + xw_t[b * GDIM + 2048 + hh];
                    g3 = gs[b * 68 + 48 + u] + xw_t[b * GDIM + 3072 + hh];
                } else {
                    g0 = gs[b * 68 + u]      + g_bias1[hh];
                    g1 = gs[b * 68 + 16 + u] + g_bias1[1024 + hh];
                    g2 = gs[b * 68 + 32 + u] + g_bias1[2048 + hh];
                    g3 = gs[b * 68 + 48 + u] + g_bias1[3072 + hh];
                }
                float ci = cc[b * HDIM + hh];
                float cn = sigm(g1) * ci + sigm(g0) * tanhf(g2);
                cc[b * HDIM + hh] = cn;
                float hn = sigm(g3) * tanhf(cn);
                hp_out[hp_idx(b, hh)] = __float2half_rn(hn);
                if (!isl0) out[(size_t)t * (B_ * HDIM) + b * HDIM + hh] = hn;
            }
        }
        grid_sync();
    }
}

// ---------------- launch ----------------
extern "C" void kernel_launch(void* const* d_in, const int* in_sizes, int n_in,
                              void* d_out, int out_size) {
    const int*   prev   = (const int*)d_in[0];
    const int*   langs  = (const int*)d_in[1];
    const float* enc_o  = (const float*)d_in[2];
    const float* enc_h  = (const float*)d_in[3];
    const float* enc_c  = (const float*)d_in[4];
    const float* embed  = (const float*)d_in[5];
    const float* W_ih0  = (const float*)d_in[6];
    const float* W_hh0  = (const float*)d_in[7];
    const float* b_ih0  = (const float*)d_in[8];
    const float* b_hh0  = (const float*)d_in[9];
    const float* W_ih1  = (const float*)d_in[10];
    const float* W_hh1  = (const float*)d_in[11];
    const float* b_ih1  = (const float*)d_in[12];
    const float* b_hh1  = (const float*)d_in[13];
    float* out = (float*)d_out;

    const int smem_bytes = DEPTH * 512 * 16 + 64 * 68 * 4;   // 96KB + 17.4KB
    static int attr_done = 0;
    if (!attr_done) {
        cudaFuncSetAttribute(persist_kernel, cudaFuncAttributeMaxDynamicSharedMemorySize,
                             smem_bytes);
        attr_done = 1;
    }

    setup_kernel<<<6144, 256>>>(enc_h, enc_c, b_ih1, b_hh1, W_hh0, W_ih1, W_hh1);
    pre0_kernel<<<GDIM, 256>>>(enc_o, langs, embed, W_ih0, b_ih0, b_hh0);
    xw_kernel<<<dim3(GDIM / 64, (SLEN * B_) / 128), 256>>>(prev, embed, W_ih0);

    persist_kernel<<<128, 256, smem_bytes>>>(out);
}